// round 1
// baseline (speedup 1.0000x reference)
#include <cuda_runtime.h>
#include <cuda_bf16.h>

// SOM layer: d2 = ||z||^2 - 2 z.P^T + ||p||^2 ; argmin over M; gather winners.
// N=32768, M=4096, D=512 (derived from in_sizes; D fixed by the model).
//
// Round 1: exact-fp32 SIMT GEMM (128x128x16 tile, 8x8 per thread) with fused
// per-row running argmin and in-kernel winner gather. Tensor cores come next
// round (bf16 coarse + fp32 refine) once numerics of the argmin are protected.

#define DDIM 512
#define MAXM 4096
#define MAXN 32768

// Scratch (allocation-free requirement -> device globals)
__device__ float g_p2[MAXM];
__device__ float g_z2[MAXN];

// ---------------------------------------------------------------------------
// Row sum-of-squares: one warp per row, 512 floats -> float4 loads + shfl tree
// ---------------------------------------------------------------------------
__global__ void sq_p_kernel(const float* __restrict__ p, int rows) {
    int warp = (blockIdx.x * blockDim.x + threadIdx.x) >> 5;
    int lane = threadIdx.x & 31;
    if (warp >= rows) return;
    const float4* xr = reinterpret_cast<const float4*>(p) + (size_t)warp * (DDIM / 4);
    float s = 0.f;
#pragma unroll
    for (int i = 0; i < (DDIM / 4) / 32; i++) {
        float4 v = xr[lane + i * 32];
        s += v.x * v.x + v.y * v.y + v.z * v.z + v.w * v.w;
    }
#pragma unroll
    for (int o = 16; o; o >>= 1) s += __shfl_xor_sync(0xffffffffu, s, o);
    if (lane == 0) g_p2[warp] = s;
}

__global__ void sq_z_kernel(const float* __restrict__ z, int rows) {
    int warp = (blockIdx.x * blockDim.x + threadIdx.x) >> 5;
    int lane = threadIdx.x & 31;
    if (warp >= rows) return;
    const float4* xr = reinterpret_cast<const float4*>(z) + (size_t)warp * (DDIM / 4);
    float s = 0.f;
#pragma unroll
    for (int i = 0; i < (DDIM / 4) / 32; i++) {
        float4 v = xr[lane + i * 32];
        s += v.x * v.x + v.y * v.y + v.z * v.z + v.w * v.w;
    }
#pragma unroll
    for (int o = 16; o; o >>= 1) s += __shfl_xor_sync(0xffffffffu, s, o);
    if (lane == 0) g_z2[warp] = s;
}

// ---------------------------------------------------------------------------
// Main: per block 128 rows of z. Loop over all prototype tiles of 128,
// full fp32 GEMM accumulate, score epilogue with running argmin, then
// cross-thread argmin reduce + winner gather.
// Thread layout: 256 threads as 16x16; thread (tx,ty) owns rows ty*8..+7,
// cols tx*8..+7 of the 128x128 tile.
// ---------------------------------------------------------------------------
__global__ __launch_bounds__(256, 2)
void som_main_kernel(const float* __restrict__ z,
                     const float* __restrict__ proto,
                     int M,
                     float* __restrict__ outW,      // winners [N,512] or null
                     float* __restrict__ outIdxF,   // idx as float or null
                     int*   __restrict__ outIdxI) { // idx as int or null
    __shared__ float As[16][128];
    __shared__ float Bs[16][128];
    __shared__ int sIdx[128];

    const int tid = threadIdx.x;
    const int tx = tid & 15;
    const int ty = tid >> 4;
    const int blockRow = blockIdx.x * 128;

    const float* zb = z + (size_t)blockRow * DDIM;

    float bestV[8];
    int   bestI[8];
#pragma unroll
    for (int r = 0; r < 8; r++) { bestV[r] = 3.4e38f; bestI[r] = 0; }

    float z2v[8];
#pragma unroll
    for (int r = 0; r < 8; r++) z2v[r] = g_z2[blockRow + ty * 8 + r];

    const int KT = DDIM / 16;  // 32 k-tiles

    for (int nt = 0; nt < M / 128; nt++) {
        const float* pb = proto + (size_t)(nt * 128) * DDIM;

        float acc[8][8];
#pragma unroll
        for (int r = 0; r < 8; r++)
#pragma unroll
            for (int c = 0; c < 8; c++) acc[r][c] = 0.f;

        // Register prefetch of the first k-tile.
        // Element mapping: linear float4 i = tid + j*256 ; row = i>>2, kq = i&3
        float4 ra[2], rb[2];
#pragma unroll
        for (int j = 0; j < 2; j++) {
            int i = tid + j * 256;
            int row = i >> 2, kq = i & 3;
            ra[j] = *reinterpret_cast<const float4*>(zb + (size_t)row * DDIM + kq * 4);
            rb[j] = *reinterpret_cast<const float4*>(pb + (size_t)row * DDIM + kq * 4);
        }

        for (int kt = 0; kt < KT; kt++) {
            // Store prefetched tile (transposed: [k][m]) so compute reads are
            // contiguous float4 along m/n.
#pragma unroll
            for (int j = 0; j < 2; j++) {
                int i = tid + j * 256;
                int row = i >> 2, kq = i & 3;
                As[kq * 4 + 0][row] = ra[j].x;
                As[kq * 4 + 1][row] = ra[j].y;
                As[kq * 4 + 2][row] = ra[j].z;
                As[kq * 4 + 3][row] = ra[j].w;
                Bs[kq * 4 + 0][row] = rb[j].x;
                Bs[kq * 4 + 1][row] = rb[j].y;
                Bs[kq * 4 + 2][row] = rb[j].z;
                Bs[kq * 4 + 3][row] = rb[j].w;
            }
            __syncthreads();

            // Prefetch next k-tile from global while computing this one.
            if (kt + 1 < KT) {
                int koff = (kt + 1) * 16;
#pragma unroll
                for (int j = 0; j < 2; j++) {
                    int i = tid + j * 256;
                    int row = i >> 2, kq = i & 3;
                    ra[j] = *reinterpret_cast<const float4*>(zb + (size_t)row * DDIM + koff + kq * 4);
                    rb[j] = *reinterpret_cast<const float4*>(pb + (size_t)row * DDIM + koff + kq * 4);
                }
            }

#pragma unroll
            for (int kk = 0; kk < 16; kk++) {
                float a0[8], b0[8];
                *reinterpret_cast<float4*>(&a0[0]) = *reinterpret_cast<const float4*>(&As[kk][ty * 8]);
                *reinterpret_cast<float4*>(&a0[4]) = *reinterpret_cast<const float4*>(&As[kk][ty * 8 + 4]);
                *reinterpret_cast<float4*>(&b0[0]) = *reinterpret_cast<const float4*>(&Bs[kk][tx * 8]);
                *reinterpret_cast<float4*>(&b0[4]) = *reinterpret_cast<const float4*>(&Bs[kk][tx * 8 + 4]);
#pragma unroll
                for (int r = 0; r < 8; r++)
#pragma unroll
                    for (int c = 0; c < 8; c++)
                        acc[r][c] = fmaf(a0[r], b0[c], acc[r][c]);
            }
            __syncthreads();
        }

        // Score epilogue: d = (z2 - 2*dot) + p2  (same association as reference;
        // 2*dot is exact in fp32 so fused fma(-2,dot,z2) matches the reference's
        // rounding). Running per-thread argmin, earliest index on exact ties.
#pragma unroll
        for (int c = 0; c < 8; c++) {
            float p2v = g_p2[nt * 128 + tx * 8 + c];
            int idx = nt * 128 + tx * 8 + c;
#pragma unroll
            for (int r = 0; r < 8; r++) {
                float s = z2v[r] - 2.0f * acc[r][c];
                float d = s + p2v;
                if (d < bestV[r]) { bestV[r] = d; bestI[r] = idx; }
            }
        }
    }

    // Cross-thread argmin: the 16 lanes sharing a ty (a half-warp) own the same
    // 8 rows; butterfly over 4 bits stays inside the half-warp.
#pragma unroll
    for (int r = 0; r < 8; r++) {
        float v = bestV[r];
        int id = bestI[r];
#pragma unroll
        for (int o = 8; o; o >>= 1) {
            float ov = __shfl_xor_sync(0xffffffffu, v, o);
            int oi = __shfl_xor_sync(0xffffffffu, id, o);
            if (ov < v || (ov == v && oi < id)) { v = ov; id = oi; }
        }
        if (tx == 0) sIdx[ty * 8 + r] = id;
    }
    __syncthreads();

    // Index outputs
    if (tid < 128) {
        int id = sIdx[tid];
        int grow = blockRow + tid;
        if (outIdxF) outIdxF[grow] = (float)id;
        if (outIdxI) outIdxI[grow] = id;
    }

    // Winner gather: 128 rows x 512 floats, float4, fully coalesced.
    if (outW) {
        const float4* p4 = reinterpret_cast<const float4*>(proto);
        float4* o4 = reinterpret_cast<float4*>(outW) + (size_t)blockRow * (DDIM / 4);
        for (int i = tid; i < 128 * (DDIM / 4); i += 256) {
            int row = i >> 7;       // /128
            int c = i & 127;
            int pidx = sIdx[row];
            o4[row * (DDIM / 4) + c] = p4[(size_t)pidx * (DDIM / 4) + c];
        }
    }
}

// ---------------------------------------------------------------------------
extern "C" void kernel_launch(void* const* d_in, const int* in_sizes, int n_in,
                              void* d_out, int out_size) {
    const float* z = (const float*)d_in[0];
    const float* p = (const float*)d_in[1];
    int N = in_sizes[0] / DDIM;
    int M = in_sizes[1] / DDIM;

    // sum-of-squares precompute into device globals
    sq_p_kernel<<<(M * 32 + 255) / 256, 256>>>(p, M);
    sq_z_kernel<<<(N * 32 + 255) / 256, 256>>>(z, N);

    // Output layout handling: reference returns (winners [N,D], min_idx [N]).
    // Most likely out = concat as float32. Fall back gracefully otherwise.
    float* outW = nullptr;
    float* outIdxF = nullptr;
    int* outIdxI = nullptr;
    long long nd = (long long)N * DDIM;
    if ((long long)out_size >= nd) {
        outW = (float*)d_out;
        if ((long long)out_size >= nd + N) outIdxF = (float*)d_out + nd;
    } else if (out_size == N) {
        outIdxI = (int*)d_out;
    }

    som_main_kernel<<<N / 128, 256>>>(z, p, M, outW, outIdxF, outIdxI);
}

// round 3
// speedup vs baseline: 7.0779x; 7.0779x over previous
#include <cuda_runtime.h>
#include <cuda_bf16.h>
#include <cstdint>

// SOM layer: coarse bf16 mma.sync GEMM (scores + candidate capture) then
// exact fp32 refinement of candidates -> argmin identical to reference.
// tcgen05 unusable in this toolchain (PTX pass targets compute_103 w/o 'a'),
// so tensor work goes through mma.sync.m16n8k16 (HMMA).

#define DDIM 512
#define MAXN 32768
#define MAXM 4096
#define CAND_CAP 64
#define COARSE_THR 1.5f

#define BM 128
#define BN 128
#define BK 32
#define PADK 40            // bf16 row stride in smem (32 data + 8 pad) -> conflict-free
#define NTHREADS 128       // 4 warps, 2x2 warp grid, warp tile 64x64

// ---------------- device global scratch (allocation-free rule) --------------
__device__ float g_p2[MAXM];
__device__ float g_z2[MAXN];
__device__ __align__(128) __nv_bfloat16 g_zbf[MAXN * DDIM];   // 32MB
__device__ __align__(128) __nv_bfloat16 g_pbf[MAXM * DDIM];   // 4MB
__device__ float    g_cval[(size_t)MAXN * CAND_CAP];
__device__ int      g_cidx[(size_t)MAXN * CAND_CAP];
__device__ int      g_ccnt[MAXN];
__device__ unsigned g_best[MAXN];    // uint-encoded positive float running min

// ---------------- helpers ----------------------------------------------------
__device__ __forceinline__ uint32_t smem_u32(const void* p) {
    uint32_t a;
    asm("{ .reg .u64 t; cvta.to.shared.u64 t, %1; cvt.u32.u64 %0, t; }"
        : "=r"(a) : "l"(p));
    return a;
}
__device__ __forceinline__ void cp16(uint32_t dst, const void* src) {
    asm volatile("cp.async.cg.shared.global [%0], [%1], 16;" :: "r"(dst), "l"(src));
}
__device__ __forceinline__ void mma16816(float* c, const uint32_t* a,
                                         uint32_t b0, uint32_t b1) {
    asm volatile(
        "mma.sync.aligned.m16n8k16.row.col.f32.bf16.bf16.f32 "
        "{%0,%1,%2,%3}, {%4,%5,%6,%7}, {%8,%9}, {%0,%1,%2,%3};"
        : "+f"(c[0]), "+f"(c[1]), "+f"(c[2]), "+f"(c[3])
        : "r"(a[0]), "r"(a[1]), "r"(a[2]), "r"(a[3]), "r"(b0), "r"(b1));
}

// ---------------- init / precompute kernels ----------------------------------
__global__ void zero_kernel(int n) {
    int i = blockIdx.x * blockDim.x + threadIdx.x;
    if (i < n) { g_ccnt[i] = 0; g_best[i] = 0x7F800000u; }
}

__global__ void sq_z_kernel(const float* __restrict__ x, int rows) {
    int warp = (blockIdx.x * blockDim.x + threadIdx.x) >> 5;
    int lane = threadIdx.x & 31;
    if (warp >= rows) return;
    const float4* xr = reinterpret_cast<const float4*>(x) + (size_t)warp * (DDIM / 4);
    float s = 0.f;
#pragma unroll
    for (int i = 0; i < (DDIM / 4) / 32; i++) {
        float4 v = xr[lane + i * 32];
        s += v.x * v.x + v.y * v.y + v.z * v.z + v.w * v.w;
    }
#pragma unroll
    for (int o = 16; o; o >>= 1) s += __shfl_xor_sync(0xffffffffu, s, o);
    if (lane == 0) g_z2[warp] = s;
}
__global__ void sq_p_kernel(const float* __restrict__ x, int rows) {
    int warp = (blockIdx.x * blockDim.x + threadIdx.x) >> 5;
    int lane = threadIdx.x & 31;
    if (warp >= rows) return;
    const float4* xr = reinterpret_cast<const float4*>(x) + (size_t)warp * (DDIM / 4);
    float s = 0.f;
#pragma unroll
    for (int i = 0; i < (DDIM / 4) / 32; i++) {
        float4 v = xr[lane + i * 32];
        s += v.x * v.x + v.y * v.y + v.z * v.z + v.w * v.w;
    }
#pragma unroll
    for (int o = 16; o; o >>= 1) s += __shfl_xor_sync(0xffffffffu, s, o);
    if (lane == 0) g_p2[warp] = s;
}

__device__ __forceinline__ uint32_t packbf(float a, float b) {
    __nv_bfloat162 t = __float22bfloat162_rn(make_float2(a, b));
    return *reinterpret_cast<uint32_t*>(&t);
}
__global__ void cvt_z_kernel(const float* __restrict__ x, int n4) {
    int i = blockIdx.x * blockDim.x + threadIdx.x;
    if (i >= n4) return;
    float4 v = reinterpret_cast<const float4*>(x)[i];
    uint2 u; u.x = packbf(v.x, v.y); u.y = packbf(v.z, v.w);
    reinterpret_cast<uint2*>(g_zbf)[i] = u;
}
__global__ void cvt_p_kernel(const float* __restrict__ x, int n4) {
    int i = blockIdx.x * blockDim.x + threadIdx.x;
    if (i >= n4) return;
    float4 v = reinterpret_cast<const float4*>(x)[i];
    uint2 u; u.x = packbf(v.x, v.y); u.y = packbf(v.z, v.w);
    reinterpret_cast<uint2*>(g_pbf)[i] = u;
}

// ---------------- main coarse GEMM + candidate capture ----------------------
// grid: (N/BM row tiles, M/BN col tiles); col tiles of a row spread over waves.
__global__ __launch_bounds__(NTHREADS, 2)
void som_mma_kernel() {
    __shared__ __align__(16) __nv_bfloat16 sA[2][BM * PADK];
    __shared__ __align__(16) __nv_bfloat16 sB[2][BN * PADK];
    __shared__ unsigned srow[BM];

    const int tid = threadIdx.x;
    const int wid = tid >> 5;
    const int lane = tid & 31;
    const int wm = wid >> 1;          // 0..1 -> M half
    const int wn = wid & 1;           // 0..1 -> N half
    const int row = lane >> 2;        // 0..7
    const int qc = lane & 3;          // 0..3  (b32 column within k-frag)

    const int rowBase = blockIdx.x * BM;
    const int colBase = blockIdx.y * BN;

    const __nv_bfloat16* gA = g_zbf + (size_t)rowBase * DDIM;
    const __nv_bfloat16* gB = g_pbf + (size_t)colBase * DDIM;

    const uint32_t aAddr0 = smem_u32(&sA[0][0]);
    const uint32_t bAddr0 = smem_u32(&sB[0][0]);

    if (tid < BM) srow[tid] = 0xFFFFFFFFu;

    float acc[4][8][4];
#pragma unroll
    for (int mi = 0; mi < 4; mi++)
#pragma unroll
        for (int ni = 0; ni < 8; ni++)
#pragma unroll
            for (int c = 0; c < 4; c++) acc[mi][ni][c] = 0.f;

    const int KT = DDIM / BK;  // 16

    // ---- cp.async stage loader: 8 x 16B per thread --------------------------
    auto loadStage = [&](int s, int kt) {
        const uint32_t aAddr = aAddr0 + s * (BM * PADK * 2);
        const uint32_t bAddr = bAddr0 + s * (BN * PADK * 2);
#pragma unroll
        for (int i = 0; i < 4; i++) {
            int ch = tid + i * NTHREADS;       // 0..511
            int r = ch >> 2, c = ch & 3;
            cp16(aAddr + r * (PADK * 2) + c * 16,
                 gA + (size_t)r * DDIM + kt * BK + c * 8);
        }
#pragma unroll
        for (int i = 0; i < 4; i++) {
            int ch = tid + i * NTHREADS;
            int r = ch >> 2, c = ch & 3;
            cp16(bAddr + r * (PADK * 2) + c * 16,
                 gB + (size_t)r * DDIM + kt * BK + c * 8);
        }
    };

    loadStage(0, 0);
    asm volatile("cp.async.commit_group;");

    int s = 0;
    for (int kt = 0; kt < KT; kt++) {
        if (kt + 1 < KT) {
            loadStage(s ^ 1, kt + 1);
            asm volatile("cp.async.commit_group;");
            asm volatile("cp.async.wait_group 1;");
        } else {
            asm volatile("cp.async.wait_group 0;");
        }
        __syncthreads();

        const uint32_t* As32 = reinterpret_cast<const uint32_t*>(&sA[s][0]);
        const uint32_t* Bs32 = reinterpret_cast<const uint32_t*>(&sB[s][0]);
#pragma unroll
        for (int kf = 0; kf < 2; kf++) {
            uint32_t a[4][4];
#pragma unroll
            for (int mi = 0; mi < 4; mi++) {
                const uint32_t* ab = As32 + (wm * 64 + mi * 16 + row) * (PADK / 2)
                                   + kf * 8 + qc;
                a[mi][0] = ab[0];
                a[mi][1] = ab[8 * (PADK / 2)];
                a[mi][2] = ab[4];
                a[mi][3] = ab[8 * (PADK / 2) + 4];
            }
#pragma unroll
            for (int ni = 0; ni < 8; ni++) {
                const uint32_t* bb = Bs32 + (wn * 64 + ni * 8 + row) * (PADK / 2)
                                   + kf * 8 + qc;
                uint32_t b0 = bb[0], b1 = bb[4];
#pragma unroll
                for (int mi = 0; mi < 4; mi++)
                    mma16816(acc[mi][ni], a[mi], b0, b1);
            }
        }
        __syncthreads();
        s ^= 1;
    }

    // ---- epilogue: d = z2 - 2*dot + p2, per-row min, candidate append -------
#pragma unroll
    for (int mi = 0; mi < 4; mi++) {
#pragma unroll
        for (int h = 0; h < 2; h++) {
            int lrow = wm * 64 + mi * 16 + row + h * 8;
            float z2v = g_z2[rowBase + lrow];
            float tmin = 3.4e38f;
#pragma unroll
            for (int ni = 0; ni < 8; ni++) {
                int gcol = colBase + wn * 64 + ni * 8 + 2 * qc;
                float d0 = (z2v - 2.0f * acc[mi][ni][2 * h])     + __ldg(&g_p2[gcol]);
                float d1 = (z2v - 2.0f * acc[mi][ni][2 * h + 1]) + __ldg(&g_p2[gcol + 1]);
                acc[mi][ni][2 * h] = d0;
                acc[mi][ni][2 * h + 1] = d1;
                tmin = fminf(tmin, fminf(d0, d1));
            }
            atomicMin(&srow[lrow], __float_as_uint(tmin));
        }
    }
    __syncthreads();

    // publish CTA row minima to global running best
    if (tid < BM) atomicMin(&g_best[rowBase + tid], srow[tid]);

    // append candidates within margin of best known
#pragma unroll
    for (int mi = 0; mi < 4; mi++) {
#pragma unroll
        for (int h = 0; h < 2; h++) {
            int lrow = wm * 64 + mi * 16 + row + h * 8;
            int grow = rowBase + lrow;
            float gb = fminf(__uint_as_float(g_best[grow]),
                             __uint_as_float(srow[lrow]));
            float thr = gb + COARSE_THR;
#pragma unroll
            for (int ni = 0; ni < 8; ni++) {
                int gcol = colBase + wn * 64 + ni * 8 + 2 * qc;
#pragma unroll
                for (int e = 0; e < 2; e++) {
                    float d = acc[mi][ni][2 * h + e];
                    if (d < thr) {
                        int slot = atomicAdd(&g_ccnt[grow], 1);
                        if (slot < CAND_CAP) {
                            g_cval[(size_t)grow * CAND_CAP + slot] = d;
                            g_cidx[(size_t)grow * CAND_CAP + slot] = gcol + e;
                        }
                    }
                }
            }
        }
    }
}

// ---------------- exact refinement + output ---------------------------------
__global__ void refine_kernel(const float* __restrict__ z,
                              const float* __restrict__ proto, int Mtot,
                              float* __restrict__ outW,
                              float* __restrict__ outIdxF,
                              int* __restrict__ outIdxI) {
    int warp = (blockIdx.x * blockDim.x + threadIdx.x) >> 5;
    int lane = threadIdx.x & 31;
    const int row = warp;
    const float z2 = g_z2[row];

    float4 zr[4];
#pragma unroll
    for (int i = 0; i < 4; i++)
        zr[i] = reinterpret_cast<const float4*>(z + (size_t)row * DDIM)[i * 32 + lane];

    int cnt = g_ccnt[row];
    float bestD = 3.4e38f;
    int bestI = 0;

    if (cnt <= CAND_CAP) {
        for (int k = 0; k < cnt; k++) {
            int c = g_cidx[(size_t)row * CAND_CAP + k];
            const float4* pr = reinterpret_cast<const float4*>(proto + (size_t)c * DDIM);
            float dot = 0.f;
#pragma unroll
            for (int i = 0; i < 4; i++) {
                float4 pv = pr[i * 32 + lane];
                dot += zr[i].x * pv.x + zr[i].y * pv.y + zr[i].z * pv.z + zr[i].w * pv.w;
            }
#pragma unroll
            for (int o = 16; o; o >>= 1) dot += __shfl_xor_sync(0xffffffffu, dot, o);
            float d = (z2 - 2.0f * dot) + __ldg(&g_p2[c]);
            if (d < bestD || (d == bestD && c < bestI)) { bestD = d; bestI = c; }
        }
    } else {
        // overflow (rare): exact scan of all columns
        for (int c = 0; c < Mtot; c++) {
            const float4* pr = reinterpret_cast<const float4*>(proto + (size_t)c * DDIM);
            float dot = 0.f;
#pragma unroll
            for (int i = 0; i < 4; i++) {
                float4 pv = pr[i * 32 + lane];
                dot += zr[i].x * pv.x + zr[i].y * pv.y + zr[i].z * pv.z + zr[i].w * pv.w;
            }
#pragma unroll
            for (int o = 16; o; o >>= 1) dot += __shfl_xor_sync(0xffffffffu, dot, o);
            float d = (z2 - 2.0f * dot) + __ldg(&g_p2[c]);
            if (d < bestD) { bestD = d; bestI = c; }
        }
    }

    if (lane == 0) {
        if (outIdxF) outIdxF[row] = (float)bestI;
        if (outIdxI) outIdxI[row] = bestI;
    }
    if (outW) {
        const float4* pr = reinterpret_cast<const float4*>(proto + (size_t)bestI * DDIM);
        float4* ow = reinterpret_cast<float4*>(outW + (size_t)row * DDIM);
#pragma unroll
        for (int i = 0; i < 4; i++) ow[i * 32 + lane] = pr[i * 32 + lane];
    }
}

// ---------------------------------------------------------------------------
extern "C" void kernel_launch(void* const* d_in, const int* in_sizes, int n_in,
                              void* d_out, int out_size) {
    const float* z = (const float*)d_in[0];
    const float* p = (const float*)d_in[1];
    int N = in_sizes[0] / DDIM;
    int M = in_sizes[1] / DDIM;

    zero_kernel<<<(N + 255) / 256, 256>>>(N);
    sq_p_kernel<<<(M * 32 + 255) / 256, 256>>>(p, M);
    sq_z_kernel<<<(N * 32 + 255) / 256, 256>>>(z, N);
    cvt_p_kernel<<<(M * (DDIM / 4) + 255) / 256, 256>>>(p, M * (DDIM / 4));
    cvt_z_kernel<<<(N * (DDIM / 4) + 255) / 256, 256>>>(z, N * (DDIM / 4));

    dim3 grid(N / BM, M / BN);   // x = row tiles (fast), y = col tiles
    som_mma_kernel<<<grid, NTHREADS>>>();

    // output layout (validated in R1): winners [N,512] fp32, then idx
    float* outW = nullptr;
    float* outIdxF = nullptr;
    int* outIdxI = nullptr;
    long long nd = (long long)N * DDIM;
    if ((long long)out_size >= nd) {
        outW = (float*)d_out;
        if ((long long)out_size >= nd + N) outIdxF = (float*)d_out + nd;
    } else if (out_size == N) {
        outIdxI = (int*)d_out;
    }

    refine_kernel<<<(N * 32) / 256, 256>>>(z, p, M, outW, outIdxF, outIdxI);
}